// round 6
// baseline (speedup 1.0000x reference)
#include <cuda_runtime.h>
#include <cuda_bf16.h>
#include <cstdint>

// ---------------------------------------------------------------------------
// Problem constants
// ---------------------------------------------------------------------------
#define BATCH 8
#define CH    512
#define LEN   8192
#define PADL  8
#define LPAD  (LEN + 2*PADL)          // 8208
#define KTOT  3072                    // 3 taps * 512 ch * 2 halves
#define WELEM (512*512*3)             // 786432 elems per weight tensor

// conv tiling: BM=128, BN=256, 8 warps, warp tile 64m x 64n
#define BM 128
#define BN 256
#define BK 64                         // k per chunk (32 u32 pair-rows)
#define NCHUNK (KTOT / BK)            // 48
#define STAGES 3
#define ASTR 72                       // A smem row stride (bf16): 64 + 8 pad
#define BSTR 264                      // B smem row stride (u32): 256 + 8 pad (==8 mod 32)
#define A_BYTES (BM * ASTR * 2)       // 18432
#define B_BYTES (32 * BSTR * 4)       // 33792
#define STAGE_BYTES (A_BYTES + B_BYTES)          // 52224
#define SMEM_TOTAL (STAGES * STAGE_BYTES)        // 156672

// ---------------------------------------------------------------------------
// Scratch (device globals — no allocation allowed)
// ---------------------------------------------------------------------------
__device__ uint32_t       g_X2[(size_t)BATCH*CH*LPAD];   // split input  {hi,lo} u32
__device__ uint32_t       g_H2[(size_t)BATCH*CH*LPAD];   // split hidden {hi,lo} u32
__device__ __nv_bfloat16  g_Wq[(size_t)6*512*KTOT];      // ternary weights, k=(tap,c,half)
__device__ float          g_scales[6];

// ---------------------------------------------------------------------------
// Helpers
// ---------------------------------------------------------------------------
__device__ __forceinline__ uint32_t smem_u32(const void* p) {
    return (uint32_t)__cvta_generic_to_shared(p);
}
__device__ __forceinline__ uint32_t packsplit(float v) {
    __nv_bfloat16 h = __float2bfloat16(v);
    float r = v - __bfloat162float(h);
    __nv_bfloat16 lo = __float2bfloat16(r);
    return (uint32_t)__bfloat16_as_ushort(h) | ((uint32_t)__bfloat16_as_ushort(lo) << 16);
}
__device__ __forceinline__ void cp16(uint32_t dst, const void* src) {
    asm volatile("cp.async.cg.shared.global [%0], [%1], 16;\n" :: "r"(dst), "l"(src));
}
__device__ __forceinline__ void cp4(uint32_t dst, const void* src) {
    asm volatile("cp.async.ca.shared.global [%0], [%1], 4;\n" :: "r"(dst), "l"(src));
}
__device__ __forceinline__ void ldmA(uint32_t a[4], uint32_t addr) {
    asm volatile("ldmatrix.sync.aligned.m8n8.x4.shared.b16 {%0,%1,%2,%3}, [%4];\n"
                 : "=r"(a[0]), "=r"(a[1]), "=r"(a[2]), "=r"(a[3]) : "r"(addr));
}
__device__ __forceinline__ void mma16816(float c[4], const uint32_t a[4], const uint32_t b[2]) {
    asm volatile(
        "mma.sync.aligned.m16n8k16.row.col.f32.bf16.bf16.f32 "
        "{%0,%1,%2,%3}, {%4,%5,%6,%7}, {%8,%9}, {%0,%1,%2,%3};\n"
        : "+f"(c[0]), "+f"(c[1]), "+f"(c[2]), "+f"(c[3])
        : "r"(a[0]), "r"(a[1]), "r"(a[2]), "r"(a[3]), "r"(b[0]), "r"(b[1]));
}

// ---------------------------------------------------------------------------
// Weight prep: absmean scale (single launch, deterministic tree reduction)
// grid: 6 blocks x 1024 threads
// ---------------------------------------------------------------------------
__global__ void scales_all_kernel(const float* w0, const float* w1, const float* w2,
                                  const float* w3, const float* w4, const float* w5) {
    const float* ws[6] = {w0, w1, w2, w3, w4, w5};
    const float* w = ws[blockIdx.x];
    __shared__ float red[1024];
    float s = 0.f;
    for (int i = threadIdx.x; i < WELEM; i += 1024) s += fabsf(w[i]);
    red[threadIdx.x] = s;
    __syncthreads();
    for (int o = 512; o; o >>= 1) {
        if (threadIdx.x < o) red[threadIdx.x] += red[threadIdx.x + o];
        __syncthreads();
    }
    if (threadIdx.x == 0) g_scales[blockIdx.x] = red[0] / (float)WELEM + 1e-5f;
}

__global__ void quant_kernel(const float* w0, const float* w1, const float* w2,
                             const float* w3, const float* w4, const float* w5) {
    const float* ws[6] = {w0, w1, w2, w3, w4, w5};
    size_t idx = (size_t)blockIdx.x * 256 + threadIdx.x;
    if (idx >= (size_t)6 * WELEM) return;
    int widx = (int)(idx / WELEM);
    int rem  = (int)(idx % WELEM);
    int o    = rem / 1536;
    int r2   = rem % 1536;
    int tap  = r2 / 512;
    int cc   = r2 % 512;
    float scale = g_scales[widx];
    float v = ws[widx][((size_t)o * 512 + cc) * 3 + tap];
    float q = rintf(v / scale);                   // round-half-even, matches jnp.round
    q = fminf(1.f, fmaxf(-1.f, q));
    __nv_bfloat16 qb = __float2bfloat16(q);       // exact for {-1,0,1}
    size_t dst = (size_t)widx * 512 * KTOT + (size_t)o * KTOT + (size_t)tap * 1024 + cc * 2;
    g_Wq[dst]     = qb;                           // half 0 (hi)
    g_Wq[dst + 1] = qb;                           // half 1 (lo)
}

// ---------------------------------------------------------------------------
// Split fp32 -> {hi,lo} bf16 pair, into padded halo layout (+ optional copy to out)
// Also zeroes the g_H2 halo (merged former zeropad_kernel).
// grid: (ceil(LPAD/256), BATCH*CH)
// ---------------------------------------------------------------------------
__global__ void split_kernel(const float* __restrict__ src, float* __restrict__ cpy) {
    int p = blockIdx.x * 256 + threadIdx.x;
    size_t bc = blockIdx.y;
    if (blockIdx.x == 0 && threadIdx.x < 16) {
        int j = threadIdx.x;                      // halo: 0..7 and 8200..8207
        g_H2[bc * LPAD + (j < 8 ? j : LEN + j)] = 0u;
    }
    if (p >= LPAD) return;
    int l = p - PADL;
    float v = 0.f;
    bool in = (l >= 0) && (l < LEN);
    if (in) v = src[bc * LEN + l];
    g_X2[bc * LPAD + p] = packsplit(v);
    if (cpy != nullptr && in) cpy[bc * LEN + l] = v;
}

// ---------------------------------------------------------------------------
// GEMM conv kernel.  SRCSEL: 0 reads g_X2, 1 reads g_H2.
// RESID=false: epilogue = scale+bias+LeakyReLU -> split-store into g_H2
// RESID=true : epilogue = scale+bias+residual  -> fp32 store into outF
// grid: (LEN/BN, CH/BM, BATCH), block 256, dynamic smem SMEM_TOTAL
// warp grid 2(m) x 4(n); warp tile 64m x 64n; accum c[4][8][4]
// ---------------------------------------------------------------------------
template <bool RESID, int SRCSEL>
__global__ __launch_bounds__(256, 1)
void conv_kernel(const float* __restrict__ bias, int widx, int dil,
                 float* __restrict__ outF) {
    extern __shared__ char smem[];

    const int lBase = blockIdx.x * BN;
    const int oBase = blockIdx.y * BM;
    const int bIdx  = blockIdx.z;
    const int tid   = threadIdx.x;
    const int lane  = tid & 31;
    const int wid   = tid >> 5;      // 0..7
    const int wm    = wid >> 2;      // 0..1  (64 m-rows each)
    const int wn    = wid & 3;       // 0..3  (64 n-cols each)
    const int g     = lane >> 2;     // 0..7
    const int tq    = lane & 3;      // 0..3

    const __nv_bfloat16* Aw = g_Wq + (size_t)widx * 512 * KTOT;
    const uint32_t* __restrict__ Bin = (SRCSEL == 0) ? g_X2 : g_H2;

    uint32_t  aB[STAGES];
    uint32_t  bB[STAGES];
    const uint32_t* bP[STAGES];
#pragma unroll
    for (int s = 0; s < STAGES; ++s) {
        char* stg = smem + s * STAGE_BYTES;
        aB[s] = smem_u32(stg);
        bB[s] = smem_u32(stg + A_BYTES);
        bP[s] = (const uint32_t*)(stg + A_BYTES);
    }

    float c[4][8][4];
#pragma unroll
    for (int mi = 0; mi < 4; ++mi)
#pragma unroll
        for (int ni = 0; ni < 8; ++ni)
#pragma unroll
            for (int r = 0; r < 4; ++r) c[mi][ni][r] = 0.f;

    auto loadStage = [&](int st, int kc) {
        // ---- A tile: 128 rows x 64 bf16 -> 4 x cp.async.16 per thread (1024 total)
        {
            int q = tid * 4;
#pragma unroll
            for (int u = 0; u < 4; ++u, ++q) {
                int m   = q >> 3;                 // 0..127
                int kch = q & 7;                  // 0..7 (8 bf16 each)
                cp16(aB[st] + (uint32_t)(m * ASTR + kch * 8) * 2,
                     Aw + (size_t)(oBase + m) * KTOT + kc * BK + kch * 8);
            }
        }
        // ---- B tile: 32 pair-rows x 256 u32 -> 32 x cp.async.4 per thread
        {
            int tap   = kc >> 4;                  // 16 chunks per tap
            int cB    = (kc & 15) << 5;           // 32 channels per chunk
            int shift = (tap - 1) * dil;
            const uint32_t* srcBase =
                Bin + ((size_t)(bIdx * CH + cB)) * LPAD + (PADL + lBase + shift);
#pragma unroll
            for (int j = 0; j < 32; ++j) {
                int r = tid + 256 * j;
                int p = r >> 8;                   // pair-row 0..31
                int n = r & 255;
                cp4(bB[st] + (uint32_t)(p * BSTR + n) * 4,
                    srcBase + (size_t)p * LPAD + n);
            }
        }
    };

    auto mmaStage = [&](int st) {
        const uint32_t* Bsl = bP[st];
#pragma unroll
        for (int s = 0; s < 4; ++s) {             // 4 x k16 per BK=64 chunk
            uint32_t afr[4][4];
#pragma unroll
            for (int mi = 0; mi < 4; ++mi) {
                uint32_t addr = aB[st] +
                    (uint32_t)(((wm * 64 + mi * 16 + (lane & 15)) * ASTR) +
                               s * 16 + ((lane >> 4) << 3)) * 2;
                ldmA(afr[mi], addr);
            }
            uint32_t bfr[8][2];
#pragma unroll
            for (int ni = 0; ni < 8; ++ni) {
                int col = wn * 64 + ni * 8 + g;
                bfr[ni][0] = Bsl[(s * 8 + tq) * BSTR + col];
                bfr[ni][1] = Bsl[(s * 8 + 4 + tq) * BSTR + col];
            }
#pragma unroll
            for (int mi = 0; mi < 4; ++mi)
#pragma unroll
                for (int ni = 0; ni < 8; ++ni)
                    mma16816(c[mi][ni], afr[mi], bfr[ni]);
        }
    };

    // ---- pipeline: 3 stages, 48 k-chunks, one barrier per chunk
    loadStage(0, 0);
    asm volatile("cp.async.commit_group;\n" ::: "memory");
    loadStage(1, 1);
    asm volatile("cp.async.commit_group;\n" ::: "memory");

    for (int kc = 0; kc < NCHUNK; ++kc) {
        asm volatile("cp.async.wait_group 1;\n" ::: "memory");  // stage kc ready
        __syncthreads();                                        // all warps done with stage (kc-1)%3
        if (kc + 2 < NCHUNK) loadStage((kc + 2) % STAGES, kc + 2);
        asm volatile("cp.async.commit_group;\n" ::: "memory");  // (possibly empty) keeps count uniform
        mmaStage(kc % STAGES);
    }

    // ---- epilogue
    const float scale = g_scales[widx];
#pragma unroll
    for (int mi = 0; mi < 4; ++mi) {
        int o0 = oBase + wm * 64 + mi * 16 + g;
        float bv0 = bias[o0];
        float bv1 = bias[o0 + 8];
#pragma unroll
        for (int ni = 0; ni < 8; ++ni) {
            int l = lBase + wn * 64 + ni * 8 + tq * 2;
            float v0 = c[mi][ni][0] * scale + bv0;
            float v1 = c[mi][ni][1] * scale + bv0;
            float v2 = c[mi][ni][2] * scale + bv1;
            float v3 = c[mi][ni][3] * scale + bv1;
            if (RESID) {
                size_t i0 = ((size_t)(bIdx * CH + o0)) * LEN + l;
                size_t i1 = ((size_t)(bIdx * CH + o0 + 8)) * LEN + l;
                float2 r0 = *(const float2*)(outF + i0);
                float2 r1 = *(const float2*)(outF + i1);
                *(float2*)(outF + i0) = make_float2(v0 + r0.x, v1 + r0.y);
                *(float2*)(outF + i1) = make_float2(v2 + r1.x, v3 + r1.y);
            } else {
                v0 = (v0 >= 0.f) ? v0 : 0.1f * v0;
                v1 = (v1 >= 0.f) ? v1 : 0.1f * v1;
                v2 = (v2 >= 0.f) ? v2 : 0.1f * v2;
                v3 = (v3 >= 0.f) ? v3 : 0.1f * v3;
                size_t i0 = ((size_t)(bIdx * CH + o0)) * LPAD + PADL + l;
                size_t i1 = ((size_t)(bIdx * CH + o0 + 8)) * LPAD + PADL + l;
                *(uint2*)(&g_H2[i0]) = make_uint2(packsplit(v0), packsplit(v1));
                *(uint2*)(&g_H2[i1]) = make_uint2(packsplit(v2), packsplit(v3));
            }
        }
    }
}

// ---------------------------------------------------------------------------
// Launch.  Order matters for ncu visibility: the fixed profiled slot is the
// 4th launch (index 3) -> make it the first conv kernel.
//   0: scales_all  1: quant  2: split  3: convA(branch0)  ...
// ---------------------------------------------------------------------------
extern "C" void kernel_launch(void* const* d_in, const int* in_sizes, int n_in,
                              void* d_out, int out_size) {
    const float* x = (const float*)d_in[0];
    const float* W[6];
    const float* Bv[6];
    for (int i = 0; i < 6; ++i) {
        W[i]  = (const float*)d_in[1 + 2 * i];
        Bv[i] = (const float*)d_in[2 + 2 * i];
    }
    float* out = (float*)d_out;

    // opt-in to >48KB dynamic smem (eager host-side call; idempotent, not captured)
    cudaFuncSetAttribute(conv_kernel<false, 0>,
                         cudaFuncAttributeMaxDynamicSharedMemorySize, SMEM_TOTAL);
    cudaFuncSetAttribute(conv_kernel<true, 1>,
                         cudaFuncAttributeMaxDynamicSharedMemorySize, SMEM_TOTAL);

    // weight prep (2 launches)
    scales_all_kernel<<<6, 1024>>>(W[0], W[1], W[2], W[3], W[4], W[5]);
    {
        size_t total = (size_t)6 * WELEM;
        int blocks = (int)((total + 255) / 256);
        quant_kernel<<<blocks, 256>>>(W[0], W[1], W[2], W[3], W[4], W[5]);
    }

    const dim3 cgrid(LEN / BN, CH / BM, BATCH);
    const dim3 sgrid((LPAD + 255) / 256, BATCH * CH);
    const int dils[3] = {1, 3, 5};

    for (int br = 0; br < 3; ++br) {
        // split current x (fp32) into hi/lo pairs; first branch also copies x -> out
        split_kernel<<<sgrid, 256>>>(br == 0 ? x : out, br == 0 ? out : nullptr);
        // conv A (dilated) + leaky + split-store -> g_H2
        conv_kernel<false, 0><<<cgrid, 256, SMEM_TOTAL>>>(Bv[2 * br], 2 * br, dils[br], nullptr);
        // conv B (dense) + bias + residual -> out
        conv_kernel<true, 1><<<cgrid, 256, SMEM_TOTAL>>>(Bv[2 * br + 1], 2 * br + 1, 1, out);
    }
}

// round 7
// speedup vs baseline: 1.8334x; 1.8334x over previous
#include <cuda_runtime.h>
#include <cuda_bf16.h>
#include <cstdint>

// ---------------------------------------------------------------------------
// Problem constants
// ---------------------------------------------------------------------------
#define BATCH 8
#define CH    512
#define LEN   8192
#define PADL  8
#define LPAD  (LEN + 2*PADL)          // 8208
#define KTOT  3072                    // 3 taps * 512 ch * 2 halves
#define WELEM (512*512*3)             // 786432 elems per weight tensor

// conv tiling: BM=128, BN=256, 16 warps (512 thr), warp tile 64m x 32n
#define BM 128
#define BN 256
#define BK 64                         // k per chunk (32 u32 pair-rows)
#define NCHUNK (KTOT / BK)            // 48
#define STAGES 3
#define ASTR 72                       // A smem row stride (bf16): 64 + 8 pad
#define BCOLS 272                     // B loaded cols per row: [-8, 264) u32 (halo for shift)
#define BSTR 296                      // B smem row stride (u32): 272 + 24 pad (==8 mod 32)
#define A_BYTES (BM * ASTR * 2)       // 18432
#define B_BYTES (32 * BSTR * 4)       // 37888
#define STAGE_BYTES (A_BYTES + B_BYTES)          // 56320
#define SMEM_TOTAL (STAGES * STAGE_BYTES)        // 168960
#define NB16 (32 * (BCOLS / 4))       // cp.async.16 count for B tile: 32*68 = 2176

// ---------------------------------------------------------------------------
// Scratch (device globals — no allocation allowed)
// ---------------------------------------------------------------------------
__device__ uint32_t       g_X2[(size_t)BATCH*CH*LPAD];   // split input  {hi,lo} u32
__device__ uint32_t       g_H2[(size_t)BATCH*CH*LPAD];   // split hidden {hi,lo} u32
__device__ __nv_bfloat16  g_Wq[(size_t)6*512*KTOT];      // ternary weights, k=(tap,c,half)
__device__ float          g_scales[6];

// ---------------------------------------------------------------------------
// Helpers
// ---------------------------------------------------------------------------
__device__ __forceinline__ uint32_t smem_u32(const void* p) {
    return (uint32_t)__cvta_generic_to_shared(p);
}
__device__ __forceinline__ uint32_t packsplit(float v) {
    __nv_bfloat16 h = __float2bfloat16(v);
    float r = v - __bfloat162float(h);
    __nv_bfloat16 lo = __float2bfloat16(r);
    return (uint32_t)__bfloat16_as_ushort(h) | ((uint32_t)__bfloat16_as_ushort(lo) << 16);
}
__device__ __forceinline__ void cp16(uint32_t dst, const void* src) {
    asm volatile("cp.async.cg.shared.global [%0], [%1], 16;\n" :: "r"(dst), "l"(src));
}
__device__ __forceinline__ void ldmA(uint32_t a[4], uint32_t addr) {
    asm volatile("ldmatrix.sync.aligned.m8n8.x4.shared.b16 {%0,%1,%2,%3}, [%4];\n"
                 : "=r"(a[0]), "=r"(a[1]), "=r"(a[2]), "=r"(a[3]) : "r"(addr));
}
__device__ __forceinline__ void mma16816(float c[4], const uint32_t a[4], const uint32_t b[2]) {
    asm volatile(
        "mma.sync.aligned.m16n8k16.row.col.f32.bf16.bf16.f32 "
        "{%0,%1,%2,%3}, {%4,%5,%6,%7}, {%8,%9}, {%0,%1,%2,%3};\n"
        : "+f"(c[0]), "+f"(c[1]), "+f"(c[2]), "+f"(c[3])
        : "r"(a[0]), "r"(a[1]), "r"(a[2]), "r"(a[3]), "r"(b[0]), "r"(b[1]));
}

// ---------------------------------------------------------------------------
// Weight prep: absmean scale (single launch, deterministic tree reduction)
// ---------------------------------------------------------------------------
__global__ void scales_all_kernel(const float* w0, const float* w1, const float* w2,
                                  const float* w3, const float* w4, const float* w5) {
    const float* ws[6] = {w0, w1, w2, w3, w4, w5};
    const float* w = ws[blockIdx.x];
    __shared__ float red[1024];
    float s = 0.f;
    for (int i = threadIdx.x; i < WELEM; i += 1024) s += fabsf(w[i]);
    red[threadIdx.x] = s;
    __syncthreads();
    for (int o = 512; o; o >>= 1) {
        if (threadIdx.x < o) red[threadIdx.x] += red[threadIdx.x + o];
        __syncthreads();
    }
    if (threadIdx.x == 0) g_scales[blockIdx.x] = red[0] / (float)WELEM + 1e-5f;
}

__global__ void quant_kernel(const float* w0, const float* w1, const float* w2,
                             const float* w3, const float* w4, const float* w5) {
    const float* ws[6] = {w0, w1, w2, w3, w4, w5};
    size_t idx = (size_t)blockIdx.x * 256 + threadIdx.x;
    if (idx >= (size_t)6 * WELEM) return;
    int widx = (int)(idx / WELEM);
    int rem  = (int)(idx % WELEM);
    int o    = rem / 1536;
    int r2   = rem % 1536;
    int tap  = r2 / 512;
    int cc   = r2 % 512;
    float scale = g_scales[widx];
    float v = ws[widx][((size_t)o * 512 + cc) * 3 + tap];
    float q = rintf(v / scale);                   // round-half-even, matches jnp.round
    q = fminf(1.f, fmaxf(-1.f, q));
    __nv_bfloat16 qb = __float2bfloat16(q);       // exact for {-1,0,1}
    size_t dst = (size_t)widx * 512 * KTOT + (size_t)o * KTOT + (size_t)tap * 1024 + cc * 2;
    g_Wq[dst]     = qb;                           // half 0 (hi)
    g_Wq[dst + 1] = qb;                           // half 1 (lo)
}

// ---------------------------------------------------------------------------
// Split fp32 -> {hi,lo} bf16 pair, into padded halo layout (+ optional copy to out)
// Also zeroes the g_H2 halo.
// grid: (ceil(LPAD/256), BATCH*CH)
// ---------------------------------------------------------------------------
__global__ void split_kernel(const float* __restrict__ src, float* __restrict__ cpy) {
    int p = blockIdx.x * 256 + threadIdx.x;
    size_t bc = blockIdx.y;
    if (blockIdx.x == 0 && threadIdx.x < 16) {
        int j = threadIdx.x;                      // halo: 0..7 and 8200..8207
        g_H2[bc * LPAD + (j < 8 ? j : LEN + j)] = 0u;
    }
    if (p >= LPAD) return;
    int l = p - PADL;
    float v = 0.f;
    bool in = (l >= 0) && (l < LEN);
    if (in) v = src[bc * LEN + l];
    g_X2[bc * LPAD + p] = packsplit(v);
    if (cpy != nullptr && in) cpy[bc * LEN + l] = v;
}

// ---------------------------------------------------------------------------
// GEMM conv kernel.  SRCSEL: 0 reads g_X2, 1 reads g_H2.
// RESID=false: epilogue = scale+bias+LeakyReLU -> split-store into g_H2
// RESID=true : epilogue = scale+bias+residual  -> fp32 store into outF
// grid: (LEN/BN, CH/BM, BATCH), block 512, dynamic smem SMEM_TOTAL
// warp grid 2(m) x 8(n); warp tile 64m x 32n; accum c[4][4][4]
// B tile loaded UNSHIFTED with +-8 u32 halo via cp.async.16; dilation shift is
// applied at LDS time (no alignment constraint) -> no cp.async.4 anywhere.
// ---------------------------------------------------------------------------
template <bool RESID, int SRCSEL>
__global__ __launch_bounds__(512, 1)
void conv_kernel(const float* __restrict__ bias, int widx, int dil,
                 float* __restrict__ outF) {
    extern __shared__ char smem[];

    const int lBase = blockIdx.x * BN;
    const int oBase = blockIdx.y * BM;
    const int bIdx  = blockIdx.z;
    const int tid   = threadIdx.x;
    const int lane  = tid & 31;
    const int wid   = tid >> 5;      // 0..15
    const int wm    = wid >> 3;      // 0..1  (64 m-rows each)
    const int wn    = wid & 7;       // 0..7  (32 n-cols each)
    const int g     = lane >> 2;     // 0..7
    const int tq    = lane & 3;      // 0..3

    const __nv_bfloat16* Aw = g_Wq + (size_t)widx * 512 * KTOT;
    const uint32_t* __restrict__ Bin = (SRCSEL == 0) ? g_X2 : g_H2;

    uint32_t  aB[STAGES];
    uint32_t  bB[STAGES];
    const uint32_t* bP[STAGES];
#pragma unroll
    for (int s = 0; s < STAGES; ++s) {
        char* stg = smem + s * STAGE_BYTES;
        aB[s] = smem_u32(stg);
        bB[s] = smem_u32(stg + A_BYTES);
        bP[s] = (const uint32_t*)(stg + A_BYTES);
    }

    float c[4][4][4];
#pragma unroll
    for (int mi = 0; mi < 4; ++mi)
#pragma unroll
        for (int ni = 0; ni < 4; ++ni)
#pragma unroll
            for (int r = 0; r < 4; ++r) c[mi][ni][r] = 0.f;

    auto loadStage = [&](int st, int kc) {
        // ---- A tile: 128 rows x 64 bf16 -> 2 x cp.async.16 per thread (1024 total)
        {
            int q = tid * 2;
#pragma unroll
            for (int u = 0; u < 2; ++u, ++q) {
                int m   = q >> 3;                 // 0..127
                int kch = q & 7;                  // 0..7 (8 bf16 each)
                cp16(aB[st] + (uint32_t)(m * ASTR + kch * 8) * 2,
                     Aw + (size_t)(oBase + m) * KTOT + kc * BK + kch * 8);
            }
        }
        // ---- B tile: 32 pair-rows x 272 u32 (cols [-8, 264)) -> cp.async.16
        //      2176 total = 4 full rounds of 512 + 128
        {
            int cB = (kc & 15) << 5;              // 32 channels per chunk (tap-independent base)
            const uint32_t* srcBase =
                Bin + ((size_t)(bIdx * CH + cB)) * LPAD + (PADL + lBase - 8);
#pragma unroll
            for (int j = 0; j < 5; ++j) {
                int r = tid + 512 * j;
                if (r < NB16) {
                    int p = r / (BCOLS / 4);      // pair-row 0..31
                    int q = r % (BCOLS / 4);      // 16B group 0..67
                    cp16(bB[st] + (uint32_t)(p * BSTR + q * 4) * 4,
                         srcBase + (size_t)p * LPAD + q * 4);
                }
            }
        }
    };

    auto mmaStage = [&](int st, int shift) {
        const uint32_t* Bsl = bP[st];
        const int colOfs = 8 + shift;             // halo offset + dilation shift
#pragma unroll
        for (int s = 0; s < 4; ++s) {             // 4 x k16 per BK=64 chunk
            uint32_t afr[4][4];
#pragma unroll
            for (int mi = 0; mi < 4; ++mi) {
                uint32_t addr = aB[st] +
                    (uint32_t)(((wm * 64 + mi * 16 + (lane & 15)) * ASTR) +
                               s * 16 + ((lane >> 4) << 3)) * 2;
                ldmA(afr[mi], addr);
            }
            uint32_t bfr[4][2];
#pragma unroll
            for (int ni = 0; ni < 4; ++ni) {
                int col = colOfs + wn * 32 + ni * 8 + g;
                bfr[ni][0] = Bsl[(s * 8 + tq) * BSTR + col];
                bfr[ni][1] = Bsl[(s * 8 + 4 + tq) * BSTR + col];
            }
#pragma unroll
            for (int mi = 0; mi < 4; ++mi)
#pragma unroll
                for (int ni = 0; ni < 4; ++ni)
                    mma16816(c[mi][ni], afr[mi], bfr[ni]);
        }
    };

    // ---- pipeline: 3 stages, 48 k-chunks, one barrier per chunk
    loadStage(0, 0);
    asm volatile("cp.async.commit_group;\n" ::: "memory");
    loadStage(1, 1);
    asm volatile("cp.async.commit_group;\n" ::: "memory");

    for (int kc = 0; kc < NCHUNK; ++kc) {
        asm volatile("cp.async.wait_group 1;\n" ::: "memory");  // stage kc ready
        __syncthreads();                                        // all warps done with stage (kc-1)%3
        if (kc + 2 < NCHUNK) loadStage((kc + 2) % STAGES, kc + 2);
        asm volatile("cp.async.commit_group;\n" ::: "memory");  // (possibly empty) keeps count uniform
        int tap = kc >> 4;                                      // 16 chunks per tap
        mmaStage(kc % STAGES, (tap - 1) * dil);
    }

    // ---- epilogue
    const float scale = g_scales[widx];
#pragma unroll
    for (int mi = 0; mi < 4; ++mi) {
        int o0 = oBase + wm * 64 + mi * 16 + g;
        float bv0 = bias[o0];
        float bv1 = bias[o0 + 8];
#pragma unroll
        for (int ni = 0; ni < 4; ++ni) {
            int l = lBase + wn * 32 + ni * 8 + tq * 2;
            float v0 = c[mi][ni][0] * scale + bv0;
            float v1 = c[mi][ni][1] * scale + bv0;
            float v2 = c[mi][ni][2] * scale + bv1;
            float v3 = c[mi][ni][3] * scale + bv1;
            if (RESID) {
                size_t i0 = ((size_t)(bIdx * CH + o0)) * LEN + l;
                size_t i1 = ((size_t)(bIdx * CH + o0 + 8)) * LEN + l;
                float2 r0 = *(const float2*)(outF + i0);
                float2 r1 = *(const float2*)(outF + i1);
                *(float2*)(outF + i0) = make_float2(v0 + r0.x, v1 + r0.y);
                *(float2*)(outF + i1) = make_float2(v2 + r1.x, v3 + r1.y);
            } else {
                v0 = (v0 >= 0.f) ? v0 : 0.1f * v0;
                v1 = (v1 >= 0.f) ? v1 : 0.1f * v1;
                v2 = (v2 >= 0.f) ? v2 : 0.1f * v2;
                v3 = (v3 >= 0.f) ? v3 : 0.1f * v3;
                size_t i0 = ((size_t)(bIdx * CH + o0)) * LPAD + PADL + l;
                size_t i1 = ((size_t)(bIdx * CH + o0 + 8)) * LPAD + PADL + l;
                *(uint2*)(&g_H2[i0]) = make_uint2(packsplit(v0), packsplit(v1));
                *(uint2*)(&g_H2[i1]) = make_uint2(packsplit(v2), packsplit(v3));
            }
        }
    }
}

// ---------------------------------------------------------------------------
// Launch.  ncu's fixed profiled slot is launch index 3 -> first conv kernel.
//   0: scales_all  1: quant  2: split  3: convA(branch0)  ...
// ---------------------------------------------------------------------------
extern "C" void kernel_launch(void* const* d_in, const int* in_sizes, int n_in,
                              void* d_out, int out_size) {
    const float* x = (const float*)d_in[0];
    const float* W[6];
    const float* Bv[6];
    for (int i = 0; i < 6; ++i) {
        W[i]  = (const float*)d_in[1 + 2 * i];
        Bv[i] = (const float*)d_in[2 + 2 * i];
    }
    float* out = (float*)d_out;

    // opt-in to >48KB dynamic smem (eager host-side call; idempotent, not captured)
    cudaFuncSetAttribute(conv_kernel<false, 0>,
                         cudaFuncAttributeMaxDynamicSharedMemorySize, SMEM_TOTAL);
    cudaFuncSetAttribute(conv_kernel<true, 1>,
                         cudaFuncAttributeMaxDynamicSharedMemorySize, SMEM_TOTAL);

    // weight prep (2 launches)
    scales_all_kernel<<<6, 1024>>>(W[0], W[1], W[2], W[3], W[4], W[5]);
    {
        size_t total = (size_t)6 * WELEM;
        int blocks = (int)((total + 255) / 256);
        quant_kernel<<<blocks, 256>>>(W[0], W[1], W[2], W[3], W[4], W[5]);
    }

    const dim3 cgrid(LEN / BN, CH / BM, BATCH);
    const dim3 sgrid((LPAD + 255) / 256, BATCH * CH);
    const int dils[3] = {1, 3, 5};

    for (int br = 0; br < 3; ++br) {
        // split current x (fp32) into hi/lo pairs; first branch also copies x -> out
        split_kernel<<<sgrid, 256>>>(br == 0 ? x : out, br == 0 ? out : nullptr);
        // conv A (dilated) + leaky + split-store -> g_H2
        conv_kernel<false, 0><<<cgrid, 512, SMEM_TOTAL>>>(Bv[2 * br], 2 * br, dils[br], nullptr);
        // conv B (dense) + bias + residual -> out
        conv_kernel<true, 1><<<cgrid, 512, SMEM_TOTAL>>>(Bv[2 * br + 1], 2 * br + 1, 1, out);
    }
}

// round 9
// speedup vs baseline: 1.8535x; 1.0110x over previous
#include <cuda_runtime.h>
#include <cuda_bf16.h>
#include <cstdint>

// ---------------------------------------------------------------------------
// Problem constants
// ---------------------------------------------------------------------------
#define BATCH 8
#define CH    512
#define LEN   8192
#define PADL  8
#define LPAD  (LEN + 2*PADL)          // 8208
#define KTOT  3072                    // 3 taps * 512 ch * 2 halves
#define WELEM (512*512*3)             // 786432 elems per weight tensor

// conv tiling: BM=128, BN=256, 16 warps (512 thr), warp tile 64m x 32n
// mainloop: 16 channel-chunk iterations x 3 taps (B tile shared across taps)
#define BM 128
#define BN 256
#define NCC 16                        // channel chunks (32 ch = 64 k each)
#define NSTG 2
#define ASTR 72                       // A smem row stride (bf16): 64 + 8 pad
#define ATILE (128 * ASTR * 2)        // 18432 per tap
#define BCOLS 272                     // B cols per row: [-8, 264) u32 (halo)
#define BSTR 296                      // B smem row stride (u32): ==8 mod 32
#define A_BYTES (3 * ATILE)           // 55296 (3 taps)
#define B_BYTES (32 * BSTR * 4)       // 37888
#define STAGE_BYTES (A_BYTES + B_BYTES)          // 93184
#define SMEM_TOTAL (NSTG * STAGE_BYTES)          // 186368
#define NB16 (32 * (BCOLS / 4))       // cp.async.16 count for B tile: 2176

// ---------------------------------------------------------------------------
// Scratch (device globals — no allocation allowed)
// ---------------------------------------------------------------------------
__device__ uint32_t       g_X2[(size_t)BATCH*CH*LPAD];   // split input  {hi,lo} u32
__device__ uint32_t       g_H2[(size_t)BATCH*CH*LPAD];   // split hidden {hi,lo} u32
__device__ __nv_bfloat16  g_Wq[(size_t)6*512*KTOT];      // ternary weights, k=(tap,c,half)
__device__ float          g_scales[6];

// ---------------------------------------------------------------------------
// Helpers
// ---------------------------------------------------------------------------
__device__ __forceinline__ uint32_t smem_u32(const void* p) {
    return (uint32_t)__cvta_generic_to_shared(p);
}
__device__ __forceinline__ uint32_t packsplit(float v) {
    __nv_bfloat16 h = __float2bfloat16(v);
    float r = v - __bfloat162float(h);
    __nv_bfloat16 lo = __float2bfloat16(r);
    return (uint32_t)__bfloat16_as_ushort(h) | ((uint32_t)__bfloat16_as_ushort(lo) << 16);
}
__device__ __forceinline__ void cp16(uint32_t dst, const void* src) {
    asm volatile("cp.async.cg.shared.global [%0], [%1], 16;\n" :: "r"(dst), "l"(src));
}
__device__ __forceinline__ void ldmA(uint32_t a[4], uint32_t addr) {
    asm volatile("ldmatrix.sync.aligned.m8n8.x4.shared.b16 {%0,%1,%2,%3}, [%4];\n"
                 : "=r"(a[0]), "=r"(a[1]), "=r"(a[2]), "=r"(a[3]) : "r"(addr));
}
__device__ __forceinline__ void mma16816(float c[4], const uint32_t a[4], const uint32_t b[2]) {
    asm volatile(
        "mma.sync.aligned.m16n8k16.row.col.f32.bf16.bf16.f32 "
        "{%0,%1,%2,%3}, {%4,%5,%6,%7}, {%8,%9}, {%0,%1,%2,%3};\n"
        : "+f"(c[0]), "+f"(c[1]), "+f"(c[2]), "+f"(c[3])
        : "r"(a[0]), "r"(a[1]), "r"(a[2]), "r"(a[3]), "r"(b[0]), "r"(b[1]));
}

// ---------------------------------------------------------------------------
// Weight prep: absmean scale (single launch, deterministic tree reduction)
// ---------------------------------------------------------------------------
__global__ void scales_all_kernel(const float* w0, const float* w1, const float* w2,
                                  const float* w3, const float* w4, const float* w5) {
    const float* ws[6] = {w0, w1, w2, w3, w4, w5};
    const float* w = ws[blockIdx.x];
    __shared__ float red[1024];
    float s = 0.f;
    for (int i = threadIdx.x; i < WELEM; i += 1024) s += fabsf(w[i]);
    red[threadIdx.x] = s;
    __syncthreads();
    for (int o = 512; o; o >>= 1) {
        if (threadIdx.x < o) red[threadIdx.x] += red[threadIdx.x + o];
        __syncthreads();
    }
    if (threadIdx.x == 0) g_scales[blockIdx.x] = red[0] / (float)WELEM + 1e-5f;
}

__global__ void quant_kernel(const float* w0, const float* w1, const float* w2,
                             const float* w3, const float* w4, const float* w5) {
    const float* ws[6] = {w0, w1, w2, w3, w4, w5};
    size_t idx = (size_t)blockIdx.x * 256 + threadIdx.x;
    if (idx >= (size_t)6 * WELEM) return;
    int widx = (int)(idx / WELEM);
    int rem  = (int)(idx % WELEM);
    int o    = rem / 1536;
    int r2   = rem % 1536;
    int tap  = r2 / 512;
    int cc   = r2 % 512;
    float scale = g_scales[widx];
    float v = ws[widx][((size_t)o * 512 + cc) * 3 + tap];
    float q = rintf(v / scale);                   // round-half-even, matches jnp.round
    q = fminf(1.f, fmaxf(-1.f, q));
    __nv_bfloat16 qb = __float2bfloat16(q);       // exact for {-1,0,1}
    size_t dst = (size_t)widx * 512 * KTOT + (size_t)o * KTOT + (size_t)tap * 1024 + cc * 2;
    g_Wq[dst]     = qb;                           // half 0 (hi)
    g_Wq[dst + 1] = qb;                           // half 1 (lo)
}

// ---------------------------------------------------------------------------
// Split fp32 -> {hi,lo} bf16 pair, into padded halo layout (+ optional copy to out)
// Also zeroes the g_H2 halo.  grid: (ceil(LPAD/256), BATCH*CH)
// ---------------------------------------------------------------------------
__global__ void split_kernel(const float* __restrict__ src, float* __restrict__ cpy) {
    int p = blockIdx.x * 256 + threadIdx.x;
    size_t bc = blockIdx.y;
    if (blockIdx.x == 0 && threadIdx.x < 16) {
        int j = threadIdx.x;                      // halo: 0..7 and 8200..8207
        g_H2[bc * LPAD + (j < 8 ? j : LEN + j)] = 0u;
    }
    if (p >= LPAD) return;
    int l = p - PADL;
    float v = 0.f;
    bool in = (l >= 0) && (l < LEN);
    if (in) v = src[bc * LEN + l];
    g_X2[bc * LPAD + p] = packsplit(v);
    if (cpy != nullptr && in) cpy[bc * LEN + l] = v;
}

// ---------------------------------------------------------------------------
// GEMM conv kernel.  SRCSEL: 0 reads g_X2, 1 reads g_H2.
// RESID=false: epilogue = scale+bias+LeakyReLU -> split-store into g_H2
// RESID=true : epilogue = scale+bias+residual  -> fp32 store into outF
// grid: (LEN/BN, CH/BM, BATCH), block 512, dynamic smem SMEM_TOTAL
// Mainloop: 16 channel-chunk iters; each loads ONE B (activation) tile with
// +-8 u32 halo and THREE A (weight, one per tap) tiles, then runs all 3 taps'
// MMAs against the same B tile (dilation shift applied at LDS time).
// ---------------------------------------------------------------------------
template <bool RESID, int SRCSEL>
__global__ __launch_bounds__(512, 1)
void conv_kernel(const float* __restrict__ bias, int widx, int dil,
                 float* __restrict__ outF) {
    extern __shared__ char smem[];

    const int lBase = blockIdx.x * BN;
    const int oBase = blockIdx.y * BM;
    const int bIdx  = blockIdx.z;
    const int tid   = threadIdx.x;
    const int lane  = tid & 31;
    const int wid   = tid >> 5;      // 0..15
    const int wm    = wid >> 3;      // 0..1  (64 m-rows each)
    const int wn    = wid & 7;       // 0..7  (32 n-cols each)
    const int g     = lane >> 2;     // 0..7
    const int tq    = lane & 3;      // 0..3

    const __nv_bfloat16* Aw = g_Wq + (size_t)widx * 512 * KTOT;
    const uint32_t* __restrict__ Bin = (SRCSEL == 0) ? g_X2 : g_H2;

    uint32_t  aB[NSTG];
    uint32_t  bB[NSTG];
    const uint32_t* bP[NSTG];
#pragma unroll
    for (int s = 0; s < NSTG; ++s) {
        char* stg = smem + s * STAGE_BYTES;
        aB[s] = smem_u32(stg);
        bB[s] = smem_u32(stg + A_BYTES);
        bP[s] = (const uint32_t*)(stg + A_BYTES);
    }

    float c[4][4][4];
#pragma unroll
    for (int mi = 0; mi < 4; ++mi)
#pragma unroll
        for (int ni = 0; ni < 4; ++ni)
#pragma unroll
            for (int r = 0; r < 4; ++r) c[mi][ni][r] = 0.f;

    auto loadStage = [&](int st, int cc) {
        // ---- A tiles: 3 taps x 128 rows x 64 bf16 -> 6 cp16/thread (3072)
        {
            int q = tid * 6;
#pragma unroll
            for (int u = 0; u < 6; ++u, ++q) {
                int t   = q >> 10;                // tap 0..2
                int rem = q & 1023;
                int m   = rem >> 3;               // 0..127
                int kch = rem & 7;                // 8 bf16 groups
                cp16(aB[st] + t * ATILE + (uint32_t)(m * ASTR + kch * 8) * 2,
                     Aw + (size_t)(oBase + m) * KTOT + (t * 16 + cc) * 64 + kch * 8);
            }
        }
        // ---- B tile: 32 channel rows x 272 u32 (cols [-8,264)) -> 2176 cp16
        {
            int cB = cc << 5;                     // 32 channels per chunk
            const uint32_t* srcBase =
                Bin + ((size_t)(bIdx * CH + cB)) * LPAD + (PADL + lBase - 8);
#pragma unroll
            for (int j = 0; j < 5; ++j) {
                int r = tid + 512 * j;
                if (r < NB16) {
                    int p = r / (BCOLS / 4);      // channel row 0..31
                    int q = r % (BCOLS / 4);      // 16B group 0..67
                    cp16(bB[st] + (uint32_t)(p * BSTR + q * 4) * 4,
                         srcBase + (size_t)p * LPAD + q * 4);
                }
            }
        }
    };

    auto mmaIter = [&](int st) {
        const uint32_t* Bsl = bP[st];
#pragma unroll
        for (int t = 0; t < 3; ++t) {             // taps share the B tile
            const uint32_t aBase = aB[st] + t * ATILE;
            const int colOfs = 8 + (t - 1) * dil; // halo offset + dilation shift
#pragma unroll
            for (int s = 0; s < 4; ++s) {         // 4 x k16 per 64-k chunk
                uint32_t afr[4][4];
#pragma unroll
                for (int mi = 0; mi < 4; ++mi) {
                    uint32_t addr = aBase +
                        (uint32_t)(((wm * 64 + mi * 16 + (lane & 15)) * ASTR) +
                                   s * 16 + ((lane >> 4) << 3)) * 2;
                    ldmA(afr[mi], addr);
                }
                uint32_t bfr[4][2];
#pragma unroll
                for (int ni = 0; ni < 4; ++ni) {
                    int col = colOfs + wn * 32 + ni * 8 + g;
                    bfr[ni][0] = Bsl[(s * 8 + tq) * BSTR + col];
                    bfr[ni][1] = Bsl[(s * 8 + 4 + tq) * BSTR + col];
                }
#pragma unroll
                for (int mi = 0; mi < 4; ++mi)
#pragma unroll
                    for (int ni = 0; ni < 4; ++ni)
                        mma16816(c[mi][ni], afr[mi], bfr[ni]);
            }
        }
    };

    // ---- pipeline: 2 stages, 16 iterations, one barrier per iteration
    loadStage(0, 0);
    asm volatile("cp.async.commit_group;\n" ::: "memory");

    for (int cc = 0; cc < NCC; ++cc) {
        asm volatile("cp.async.wait_group 0;\n" ::: "memory");  // stage cc ready
        __syncthreads();                          // all warps done reading stage cc^1
        if (cc + 1 < NCC) {
            loadStage((cc + 1) & 1, cc + 1);
            asm volatile("cp.async.commit_group;\n" ::: "memory");
        }
        mmaIter(cc & 1);
    }

    // ---- epilogue
    const float scale = g_scales[widx];
#pragma unroll
    for (int mi = 0; mi < 4; ++mi) {
        int o0 = oBase + wm * 64 + mi * 16 + g;
        float bv0 = bias[o0];
        float bv1 = bias[o0 + 8];
#pragma unroll
        for (int ni = 0; ni < 4; ++ni) {
            int l = lBase + wn * 32 + ni * 8 + tq * 2;
            float v0 = c[mi][ni][0] * scale + bv0;
            float v1 = c[mi][ni][1] * scale + bv0;
            float v2 = c[mi][ni][2] * scale + bv1;
            float v3 = c[mi][ni][3] * scale + bv1;
            if (RESID) {
                size_t i0 = ((size_t)(bIdx * CH + o0)) * LEN + l;
                size_t i1 = ((size_t)(bIdx * CH + o0 + 8)) * LEN + l;
                float2 r0 = *(const float2*)(outF + i0);
                float2 r1 = *(const float2*)(outF + i1);
                *(float2*)(outF + i0) = make_float2(v0 + r0.x, v1 + r0.y);
                *(float2*)(outF + i1) = make_float2(v2 + r1.x, v3 + r1.y);
            } else {
                v0 = (v0 >= 0.f) ? v0 : 0.1f * v0;
                v1 = (v1 >= 0.f) ? v1 : 0.1f * v1;
                v2 = (v2 >= 0.f) ? v2 : 0.1f * v2;
                v3 = (v3 >= 0.f) ? v3 : 0.1f * v3;
                size_t i0 = ((size_t)(bIdx * CH + o0)) * LPAD + PADL + l;
                size_t i1 = ((size_t)(bIdx * CH + o0 + 8)) * LPAD + PADL + l;
                *(uint2*)(&g_H2[i0]) = make_uint2(packsplit(v0), packsplit(v1));
                *(uint2*)(&g_H2[i1]) = make_uint2(packsplit(v2), packsplit(v3));
            }
        }
    }
}

// ---------------------------------------------------------------------------
// Launch.  ncu's fixed profiled slot is launch index 3 -> first conv kernel.
//   0: scales_all  1: quant  2: split  3: convA(branch0)  ...
// ---------------------------------------------------------------------------
extern "C" void kernel_launch(void* const* d_in, const int* in_sizes, int n_in,
                              void* d_out, int out_size) {
    const float* x = (const float*)d_in[0];
    const float* W[6];
    const float* Bv[6];
    for (int i = 0; i < 6; ++i) {
        W[i]  = (const float*)d_in[1 + 2 * i];
        Bv[i] = (const float*)d_in[2 + 2 * i];
    }
    float* out = (float*)d_out;

    // opt-in to >48KB dynamic smem (eager host-side call; idempotent, not captured)
    cudaFuncSetAttribute(conv_kernel<false, 0>,
                         cudaFuncAttributeMaxDynamicSharedMemorySize, SMEM_TOTAL);
    cudaFuncSetAttribute(conv_kernel<true, 1>,
                         cudaFuncAttributeMaxDynamicSharedMemorySize, SMEM_TOTAL);

    // weight prep (2 launches)
    scales_all_kernel<<<6, 1024>>>(W[0], W[1], W[2], W[3], W[4], W[5]);
    {
        size_t total = (size_t)6 * WELEM;
        int blocks = (int)((total + 255) / 256);
        quant_kernel<<<blocks, 256>>>(W[0], W[1], W[2], W[3], W[4], W[5]);
    }

    const dim3 cgrid(LEN / BN, CH / BM, BATCH);
    const dim3 sgrid((LPAD + 255) / 256, BATCH * CH);
    const int dils[3] = {1, 3, 5};

    for (int br = 0; br < 3; ++br) {
        // split current x (fp32) into hi/lo pairs; first branch also copies x -> out
        split_kernel<<<sgrid, 256>>>(br == 0 ? x : out, br == 0 ? out : nullptr);
        // conv A (dilated) + leaky + split-store -> g_H2
        conv_kernel<false, 0><<<cgrid, 512, SMEM_TOTAL>>>(Bv[2 * br], 2 * br, dils[br], nullptr);
        // conv B (dense) + bias + residual -> out
        conv_kernel<true, 1><<<cgrid, 512, SMEM_TOTAL>>>(Bv[2 * br + 1], 2 * br + 1, 1, out);
    }
}